// round 2
// baseline (speedup 1.0000x reference)
#include <cuda_runtime.h>
#include <cuda.h>
#include <cuda_bf16.h>
#include <cstdint>

// Problem dims (fixed by reference)
#define BB 16
#define TT 4096
#define DD 512           // K dim of GEMM / feature dim
#define EE 512           // N dim of GEMM
#define MTOT (BB*TT)     // 65536 rows

// ---------------- scratch (device globals; no allocation) ----------------
__device__ __nv_bfloat16 g_Wbf[EE * DD];  // transposed W in bf16: Wbf[e][d]
__device__ float g_scores[MTOT];          // scores[b*T + t]
__device__ float g_stats[BB * 2];         // {max, 1/sumexp} per batch

// ---------------- PTX helpers ----------------
__device__ __forceinline__ uint32_t smem_u32(const void* p) {
    uint32_t a;
    asm("{ .reg .u64 t; cvta.to.shared.u64 t, %1; cvt.u32.u64 %0, t; }" : "=r"(a) : "l"(p));
    return a;
}

#define MBARRIER_INIT(addr, cnt) \
    asm volatile("mbarrier.init.shared.b64 [%0], %1;" :: "r"((uint32_t)(addr)), "r"((uint32_t)(cnt)) : "memory")

#define MBARRIER_INVAL(addr) \
    asm volatile("mbarrier.inval.shared.b64 [%0];" :: "r"((uint32_t)(addr)) : "memory")

#define MBARRIER_EXPECT_TX(addr, bytes) \
    asm volatile("mbarrier.arrive.expect_tx.shared.b64 _, [%0], %1;" :: "r"((uint32_t)(addr)), "r"((uint32_t)(bytes)) : "memory")

#define MBARRIER_WAIT_PARITY(mbar_smem_addr, phase_parity) do { \
    uint32_t _mbar = (uint32_t)(mbar_smem_addr); \
    uint32_t _parity = (uint32_t)(phase_parity); \
    uint32_t _done; \
    asm volatile( \
        "{\n\t" \
        ".reg .pred p;\n\t" \
        "mbarrier.try_wait.parity.acquire.cta.shared::cta.b64 p, [%1], %2;\n\t" \
        "selp.b32 %0, 1, 0, p;\n\t" \
        "}" \
        : "=r"(_done) : "r"(_mbar), "r"(_parity) : "memory"); \
    if (!_done) { \
        asm volatile( \
            "{\n\t" \
            ".reg .pred P1;\n\t" \
            "WAIT_LOOP_%=:\n\t" \
            "mbarrier.try_wait.parity.acquire.cta.shared::cta.b64 P1, [%0], %1, 0x989680;\n\t" \
            "@P1 bra.uni WAIT_DONE_%=;\n\t" \
            "bra.uni WAIT_LOOP_%=;\n\t" \
            "WAIT_DONE_%=:\n\t" \
            "}" \
            :: "r"(_mbar), "r"(_parity) : "memory"); \
    } \
} while(0)

#define TMA_LOAD_2D(smem_addr, map_ptr, c0, c1, mbar) \
    asm volatile("cp.async.bulk.tensor.2d.shared::cta.global.tile.mbarrier::complete_tx::bytes " \
        "[%0], [%1, {%2, %3}], [%4];" \
        :: "r"((uint32_t)(smem_addr)), "l"(map_ptr), "r"((int)(c0)), "r"((int)(c1)), \
           "r"((uint32_t)(mbar)) : "memory")

__device__ __forceinline__ void ldsm_x4(uint32_t* r, uint32_t addr) {
    asm volatile("ldmatrix.sync.aligned.m8n8.x4.shared.b16 {%0,%1,%2,%3}, [%4];"
        : "=r"(r[0]), "=r"(r[1]), "=r"(r[2]), "=r"(r[3]) : "r"(addr));
}
__device__ __forceinline__ void ldsm_x2(uint32_t* r, uint32_t addr) {
    asm volatile("ldmatrix.sync.aligned.m8n8.x2.shared.b16 {%0,%1}, [%2];"
        : "=r"(r[0]), "=r"(r[1]) : "r"(addr));
}
__device__ __forceinline__ void mma_bf16(float* d, const uint32_t* a, const uint32_t* b) {
    asm volatile("mma.sync.aligned.m16n8k16.row.col.f32.bf16.bf16.f32 "
        "{%0,%1,%2,%3}, {%4,%5,%6,%7}, {%8,%9}, {%0,%1,%2,%3};"
        : "+f"(d[0]), "+f"(d[1]), "+f"(d[2]), "+f"(d[3])
        : "r"(a[0]), "r"(a[1]), "r"(a[2]), "r"(a[3]), "r"(b[0]), "r"(b[1]));
}
__device__ __forceinline__ float tanh_approx(float x) {
    float r;
    asm("tanh.approx.f32 %0, %1;" : "=f"(r) : "f"(x));
    return r;
}

// ---------------- kernel 0: transpose + convert W -> g_Wbf[e][d] bf16 --------
__global__ void k0_transpose(const float* __restrict__ W) {
    __shared__ float tile[32][33];
    int x0 = blockIdx.x * 32, y0 = blockIdx.y * 32;
    int tx = threadIdx.x & 31, ty = threadIdx.x >> 5;  // 256 threads = 32x8
#pragma unroll
    for (int i = 0; i < 32; i += 8) tile[ty + i][tx] = W[(y0 + ty + i) * EE + x0 + tx];
    __syncthreads();
#pragma unroll
    for (int i = 0; i < 32; i += 8)
        g_Wbf[(x0 + ty + i) * DD + y0 + tx] = __float2bfloat16(tile[tx][ty + i]);
}

// ---------------- kernel 1: fused bf16 mma GEMM + tanh + dot(v) -> scores ----
// CTA: 128 rows of x, all of K=512 resident in smem (bf16, SW128 layout).
// W streamed in N-chunks of 32 (TMA, double-buffered). 256 threads, 8 warps
// arranged 4(m) x 2(n): warp tile = 32 rows x 16 cols.
#define N_CHUNK  32
#define N_CHUNKS 16
#define W_CHUNK_BYTES 32768   // 32 n-rows x 512 k x 2B

// smem offsets
#define SM_FULL   0           // 2 mbarriers (16B)
#define SM_V      64          // 512 floats
#define SM_SCORE  2112        // 128 floats
#define SM_A      4096        // 128 rows x 512 k bf16, 8 sub-boxes of 128x128B = 131072
#define SM_W      135168      // 2 x 32768
#define SM_TOTAL1 200704

// byte offset inside a 128B-wide SW128 sub-box: row*128 + (col_bytes ^ ((row&7)<<4))
__device__ __forceinline__ uint32_t swz(uint32_t row, uint32_t col_bytes) {
    return row * 128u + (col_bytes ^ ((row & 7u) << 4));
}

__global__ void __launch_bounds__(256, 1) k1_gemm_scores(
    const __grid_constant__ CUtensorMap tma_w,
    const float* __restrict__ x,
    const float* __restrict__ att_v)
{
    extern __shared__ char smem[];
    uint32_t sb = smem_u32(smem);
    const int tid = threadIdx.x, lane = tid & 31, wid = tid >> 5;
    const int warp_m = wid >> 1, warp_n = wid & 1;

    float* vsh = (float*)(smem + SM_V);
    float* ssc = (float*)(smem + SM_SCORE);

    if (tid == 0) {
        MBARRIER_INIT(sb + SM_FULL, 1);
        MBARRIER_INIT(sb + SM_FULL + 8, 1);
    }
    for (int i = tid; i < EE; i += 256) vsh[i] = att_v[i];
    if (tid < 128) ssc[tid] = 0.0f;
    __syncthreads();

    const int m0 = blockIdx.x * 128;

    // kick W chunks 0 and 1 (8 TMA sub-box loads each: 64k x 32n, SW128)
    if (tid == 0) {
#pragma unroll
        for (int s = 0; s < 2; s++) {
            MBARRIER_EXPECT_TX(sb + SM_FULL + 8 * s, W_CHUNK_BYTES);
#pragma unroll
            for (int kb = 0; kb < 8; kb++)
                TMA_LOAD_2D(sb + SM_W + s * W_CHUNK_BYTES + kb * 4096, &tma_w,
                            kb * 64, s * N_CHUNK, sb + SM_FULL + 8 * s);
        }
    }

    // load + convert A tile: x[m0:m0+128, 0:512] fp32 -> bf16 SW128 smem
    {
        const float4* xg = (const float4*)(x + (size_t)m0 * DD);
#pragma unroll 8
        for (int i = 0; i < 64; i++) {
            int idx = tid + i * 256;
            int r = idx >> 7, c4 = idx & 127;          // c4 = float4 column
            float4 f = xg[(size_t)r * 128 + c4];
            __nv_bfloat162 lo = __floats2bfloat162_rn(f.x, f.y);
            __nv_bfloat162 hi = __floats2bfloat162_rn(f.z, f.w);
            int k = c4 * 4;
            uint32_t off = (uint32_t)SM_A + (uint32_t)(k >> 6) * 16384u + swz(r, (k & 63) * 2);
            uint2 u;
            u.x = *reinterpret_cast<uint32_t*>(&lo);
            u.y = *reinterpret_cast<uint32_t*>(&hi);
            *reinterpret_cast<uint2*>(smem + off) = u;
        }
    }
    __syncthreads();

    // precomputed per-lane ldmatrix address pieces
    // A: lanes 0-15 -> rows m+0..15, lanes 16-31 -> same rows, +16B (k+8)
    uint32_t a_base[2], a_xor[2];
#pragma unroll
    for (int mi = 0; mi < 2; mi++) {
        uint32_t row = warp_m * 32 + mi * 16 + (lane & 15);
        a_base[mi] = sb + SM_A + row * 128u;
        a_xor[mi]  = ((row & 7u) << 4) ^ ((uint32_t)(lane >> 4) << 4);
    }
    // B: lanes 0-7 -> n rows @k0, lanes 8-15 -> n rows @k0+8 (+16B)
    uint32_t b_base[2], b_xor[2];
#pragma unroll
    for (int ni = 0; ni < 2; ni++) {
        uint32_t nrow = warp_n * 16 + ni * 8 + (lane & 7);
        b_base[ni] = nrow * 128u;
        b_xor[ni]  = ((nrow & 7u) << 4) ^ (((uint32_t)(lane >> 3) & 1u) << 4);
    }

    float score[4] = {0.f, 0.f, 0.f, 0.f};

    for (int chunk = 0; chunk < N_CHUNKS; chunk++) {
        const int buf = chunk & 1;
        const int ph  = (chunk >> 1) & 1;
        const uint32_t wb = sb + SM_W + buf * W_CHUNK_BYTES;

        MBARRIER_WAIT_PARITY(sb + SM_FULL + 8 * buf, ph);

        float acc[4][4];
#pragma unroll
        for (int i = 0; i < 4; i++)
#pragma unroll
            for (int j = 0; j < 4; j++) acc[i][j] = 0.f;

        // K loop: 8 sub-boxes x 4 k16-steps
#pragma unroll 1
        for (int kb = 0; kb < 8; kb++) {
            const uint32_t akb = (uint32_t)kb * 16384u;
            const uint32_t wkb = wb + (uint32_t)kb * 4096u;
#pragma unroll
            for (int kq = 0; kq < 4; kq++) {
                const uint32_t kc = (uint32_t)kq * 32u;
                uint32_t a0[4], a1[4], b0[2], b1[2];
                ldsm_x4(a0, a_base[0] + akb + (kc ^ a_xor[0]));
                ldsm_x4(a1, a_base[1] + akb + (kc ^ a_xor[1]));
                ldsm_x2(b0, wkb + b_base[0] + (kc ^ b_xor[0]));
                ldsm_x2(b1, wkb + b_base[1] + (kc ^ b_xor[1]));
                mma_bf16(acc[0], a0, b0);
                mma_bf16(acc[1], a0, b1);
                mma_bf16(acc[2], a1, b0);
                mma_bf16(acc[3], a1, b1);
            }
        }

        // epilogue: tanh + dot with v, accumulate per-row partial scores
        {
            const int jb = chunk * N_CHUNK + warp_n * 16 + (lane & 3) * 2;
#pragma unroll
            for (int mi = 0; mi < 2; mi++)
#pragma unroll
                for (int ni = 0; ni < 2; ni++) {
                    const float* c = acc[mi * 2 + ni];
                    float v0 = vsh[jb + ni * 8];
                    float v1 = vsh[jb + ni * 8 + 1];
                    score[mi * 2 + 0] += tanh_approx(c[0]) * v0 + tanh_approx(c[1]) * v1;
                    score[mi * 2 + 1] += tanh_approx(c[2]) * v0 + tanh_approx(c[3]) * v1;
                }
        }

        __syncthreads();  // everyone done reading this W buffer
        if (chunk + 2 < N_CHUNKS && tid == 0) {
            MBARRIER_EXPECT_TX(sb + SM_FULL + 8 * buf, W_CHUNK_BYTES);
#pragma unroll
            for (int kb = 0; kb < 8; kb++)
                TMA_LOAD_2D(wb + kb * 4096, &tma_w,
                            kb * 64, (chunk + 2) * N_CHUNK, sb + SM_FULL + 8 * buf);
        }
    }

    // reduce scores: lanes sharing a row differ in (lane&3); butterfly then smem atomics
#pragma unroll
    for (int j = 0; j < 4; j++) {
        score[j] += __shfl_xor_sync(0xFFFFFFFF, score[j], 1);
        score[j] += __shfl_xor_sync(0xFFFFFFFF, score[j], 2);
    }
    if ((lane & 3) == 0) {
        int rbase = warp_m * 32 + (lane >> 2);
        atomicAdd(&ssc[rbase + 0],  score[0]);
        atomicAdd(&ssc[rbase + 8],  score[1]);
        atomicAdd(&ssc[rbase + 16], score[2]);
        atomicAdd(&ssc[rbase + 24], score[3]);
    }
    __syncthreads();
    if (tid < 128) g_scores[m0 + tid] = ssc[tid];
}

// ---------------- kernel 2: per-batch softmax stats (max, 1/sumexp) ----------
__global__ void k2_stats() {
    int b = blockIdx.x;
    __shared__ float red[256];
    float m = -1e30f;
    for (int t = threadIdx.x; t < TT; t += 256) m = fmaxf(m, g_scores[b * TT + t]);
    red[threadIdx.x] = m; __syncthreads();
    for (int s = 128; s > 0; s >>= 1) {
        if (threadIdx.x < s) red[threadIdx.x] = fmaxf(red[threadIdx.x], red[threadIdx.x + s]);
        __syncthreads();
    }
    float mx = red[0]; __syncthreads();
    float sum = 0.0f;
    for (int t = threadIdx.x; t < TT; t += 256) sum += __expf(g_scores[b * TT + t] - mx);
    red[threadIdx.x] = sum; __syncthreads();
    for (int s = 128; s > 0; s >>= 1) {
        if (threadIdx.x < s) red[threadIdx.x] += red[threadIdx.x + s];
        __syncthreads();
    }
    if (threadIdx.x == 0) { g_stats[2 * b] = mx; g_stats[2 * b + 1] = 1.0f / red[0]; }
}

// ---------------- kernel 3: weighted-sum pooling (fp32, vectorized) ----------
// grid (32 t-chunks, 16 batches), 128 threads; thread owns 4 d-columns.
__global__ void __launch_bounds__(128) k3_pool(const float* __restrict__ x,
                                               float* __restrict__ out) {
    int b = blockIdx.y;
    int t0 = blockIdx.x * 128;
    __shared__ float w_s[128];
    float mx = g_stats[2 * b], inv = g_stats[2 * b + 1];
    w_s[threadIdx.x] = __expf(g_scores[b * TT + t0 + threadIdx.x] - mx) * inv;
    __syncthreads();
    const float4* xp = (const float4*)(x + ((size_t)b * TT + t0) * DD) + threadIdx.x;
    float ax = 0.f, ay = 0.f, az = 0.f, aw = 0.f;
#pragma unroll 8
    for (int i = 0; i < 128; i++) {
        float4 f = xp[(size_t)i * 128];
        float w = w_s[i];
        ax = fmaf(w, f.x, ax); ay = fmaf(w, f.y, ay);
        az = fmaf(w, f.z, az); aw = fmaf(w, f.w, aw);
    }
    float* o = out + b * DD + threadIdx.x * 4;
    atomicAdd(o + 0, ax); atomicAdd(o + 1, ay);
    atomicAdd(o + 2, az); atomicAdd(o + 3, aw);
}

// ---------------- host ----------------
typedef CUresult (*EncodeTiledFn)(
    CUtensorMap*, CUtensorMapDataType, cuuint32_t, void*,
    const cuuint64_t*, const cuuint64_t*, const cuuint32_t*, const cuuint32_t*,
    CUtensorMapInterleave, CUtensorMapSwizzle, CUtensorMapL2promotion, CUtensorMapFloatOOBfill);

extern "C" void kernel_launch(void* const* d_in, const int* in_sizes, int n_in,
                              void* d_out, int out_size) {
    const float* x = (const float*)d_in[0];
    const float* W = (const float*)d_in[1];
    const float* v = (const float*)d_in[2];
    float* out = (float*)d_out;

    // driver TMA-encode entry point through the runtime (no -lcuda link needed)
    EncodeTiledFn encode = nullptr;
    cudaDriverEntryPointQueryResult qres;
    cudaGetDriverEntryPointByVersion("cuTensorMapEncodeTiled", (void**)&encode,
                                     12000, cudaEnableDefault, &qres);

    void* wbf_ptr = nullptr;
    cudaGetSymbolAddress(&wbf_ptr, g_Wbf);

    // transpose+convert W -> g_Wbf[e][d] bf16
    k0_transpose<<<dim3(16, 16), 256>>>(W);

    // TMA map for W: dims (k=512, n=512) bf16, box (64, 32), SW128
    CUtensorMap tma_w{};
    if (encode) {
        cuuint64_t dims[2]    = { (cuuint64_t)DD, (cuuint64_t)EE };
        cuuint64_t strides[1] = { (cuuint64_t)DD * sizeof(__nv_bfloat16) };
        cuuint32_t box[2]     = { 64, N_CHUNK };
        cuuint32_t es[2]      = { 1, 1 };
        encode(&tma_w, CU_TENSOR_MAP_DATA_TYPE_BFLOAT16, 2, wbf_ptr,
               dims, strides, box, es,
               CU_TENSOR_MAP_INTERLEAVE_NONE, CU_TENSOR_MAP_SWIZZLE_128B,
               CU_TENSOR_MAP_L2_PROMOTION_L2_128B, CU_TENSOR_MAP_FLOAT_OOB_FILL_NONE);
    }

    cudaFuncSetAttribute(k1_gemm_scores, cudaFuncAttributeMaxDynamicSharedMemorySize, SM_TOTAL1);
    k1_gemm_scores<<<MTOT / 128, 256, SM_TOTAL1>>>(tma_w, x, v);

    k2_stats<<<BB, 256>>>();

    cudaMemsetAsync(d_out, 0, (size_t)out_size * sizeof(float));
    k3_pool<<<dim3(TT / 128, BB), 128>>>(x, out);
}

// round 3
// speedup vs baseline: 1.2265x; 1.2265x over previous
#include <cuda_runtime.h>
#include <cuda.h>
#include <cuda_bf16.h>
#include <cstdint>

// Problem dims (fixed by reference)
#define BB 16
#define TT 4096
#define DD 512           // K dim of GEMM / feature dim
#define EE 512           // N dim of GEMM
#define MTOT (BB*TT)     // 65536 rows

// ---------------- scratch (device globals; no allocation) ----------------
__device__ __nv_bfloat16 g_Wbf[EE * DD];  // transposed W in bf16: Wbf[e][d]
__device__ float g_scores[MTOT];          // scores[b*T + t]
__device__ float g_stats[BB * 2];         // {max, 1/sumexp} per batch

// ---------------- PTX helpers ----------------
__device__ __forceinline__ uint32_t smem_u32(const void* p) {
    uint32_t a;
    asm("{ .reg .u64 t; cvta.to.shared.u64 t, %1; cvt.u32.u64 %0, t; }" : "=r"(a) : "l"(p));
    return a;
}

#define MBARRIER_INIT(addr, cnt) \
    asm volatile("mbarrier.init.shared.b64 [%0], %1;" :: "r"((uint32_t)(addr)), "r"((uint32_t)(cnt)) : "memory")

#define MBARRIER_EXPECT_TX(addr, bytes) \
    asm volatile("mbarrier.arrive.expect_tx.shared.b64 _, [%0], %1;" :: "r"((uint32_t)(addr)), "r"((uint32_t)(bytes)) : "memory")

#define MBARRIER_WAIT_PARITY(mbar_smem_addr, phase_parity) do { \
    uint32_t _mbar = (uint32_t)(mbar_smem_addr); \
    uint32_t _parity = (uint32_t)(phase_parity); \
    uint32_t _done; \
    asm volatile( \
        "{\n\t" \
        ".reg .pred p;\n\t" \
        "mbarrier.try_wait.parity.acquire.cta.shared::cta.b64 p, [%1], %2;\n\t" \
        "selp.b32 %0, 1, 0, p;\n\t" \
        "}" \
        : "=r"(_done) : "r"(_mbar), "r"(_parity) : "memory"); \
    if (!_done) { \
        asm volatile( \
            "{\n\t" \
            ".reg .pred P1;\n\t" \
            "WAIT_LOOP_%=:\n\t" \
            "mbarrier.try_wait.parity.acquire.cta.shared::cta.b64 P1, [%0], %1, 0x989680;\n\t" \
            "@P1 bra.uni WAIT_DONE_%=;\n\t" \
            "bra.uni WAIT_LOOP_%=;\n\t" \
            "WAIT_DONE_%=:\n\t" \
            "}" \
            :: "r"(_mbar), "r"(_parity) : "memory"); \
    } \
} while(0)

#define TMA_LOAD_2D(smem_addr, map_ptr, c0, c1, mbar) \
    asm volatile("cp.async.bulk.tensor.2d.shared::cta.global.tile.mbarrier::complete_tx::bytes " \
        "[%0], [%1, {%2, %3}], [%4];" \
        :: "r"((uint32_t)(smem_addr)), "l"(map_ptr), "r"((int)(c0)), "r"((int)(c1)), \
           "r"((uint32_t)(mbar)) : "memory")

__device__ __forceinline__ void ldsm_x4(uint32_t* r, uint32_t addr) {
    asm volatile("ldmatrix.sync.aligned.m8n8.x4.shared.b16 {%0,%1,%2,%3}, [%4];"
        : "=r"(r[0]), "=r"(r[1]), "=r"(r[2]), "=r"(r[3]) : "r"(addr));
}
__device__ __forceinline__ void mma_bf16(float* d, const uint32_t* a, const uint32_t* b) {
    asm volatile("mma.sync.aligned.m16n8k16.row.col.f32.bf16.bf16.f32 "
        "{%0,%1,%2,%3}, {%4,%5,%6,%7}, {%8,%9}, {%0,%1,%2,%3};"
        : "+f"(d[0]), "+f"(d[1]), "+f"(d[2]), "+f"(d[3])
        : "r"(a[0]), "r"(a[1]), "r"(a[2]), "r"(a[3]), "r"(b[0]), "r"(b[1]));
}
__device__ __forceinline__ float tanh_approx(float x) {
    float r;
    asm("tanh.approx.f32 %0, %1;" : "=f"(r) : "f"(x));
    return r;
}

// ---------------- kernel 0: transpose + convert W -> g_Wbf[e][d] bf16 --------
__global__ void k0_transpose(const float* __restrict__ W) {
    __shared__ float tile[32][33];
    int x0 = blockIdx.x * 32, y0 = blockIdx.y * 32;
    int tx = threadIdx.x & 31, ty = threadIdx.x >> 5;  // 256 threads = 32x8
#pragma unroll
    for (int i = 0; i < 32; i += 8) tile[ty + i][tx] = W[(y0 + ty + i) * EE + x0 + tx];
    __syncthreads();
#pragma unroll
    for (int i = 0; i < 32; i += 8)
        g_Wbf[(x0 + ty + i) * DD + y0 + tx] = __float2bfloat16(tile[tx][ty + i]);
}

// ---------------- kernel 1: fused bf16 mma GEMM + tanh + dot(v) -> scores ----
// CTA: 128 rows of x. 256 threads = 8 warps, warp tile m16 x n32 (A held in
// REGISTERS for all of K=512 -> zero A smem re-reads; only B streams).
// W streamed in N-chunks of 32 (TMA, double-buffered).
#define N_CHUNK  32
#define N_CHUNKS 16
#define W_CHUNK_BYTES 32768   // 32 n-rows x 512 k x 2B

// smem offsets
#define SM_FULL   0           // 2 mbarriers
#define SM_V      64          // 512 floats
#define SM_A      4096        // 128 rows x 512 k bf16, 8 sub-boxes of 128x128B
#define SM_W      135168      // 2 x 32768
#define SM_TOTAL1 200704

__device__ __forceinline__ uint32_t swz(uint32_t row, uint32_t col_bytes) {
    return row * 128u + (col_bytes ^ ((row & 7u) << 4));
}

__global__ void __launch_bounds__(256, 1) k1_gemm_scores(
    const __grid_constant__ CUtensorMap tma_w,
    const float* __restrict__ x,
    const float* __restrict__ att_v)
{
    extern __shared__ char smem[];
    uint32_t sb = smem_u32(smem);
    const int tid = threadIdx.x, lane = tid & 31, wid = tid >> 5;

    float* vsh = (float*)(smem + SM_V);

    if (tid == 0) {
        MBARRIER_INIT(sb + SM_FULL, 1);
        MBARRIER_INIT(sb + SM_FULL + 8, 1);
    }
    for (int i = tid; i < EE; i += 256) vsh[i] = att_v[i];
    __syncthreads();

    const int m0 = blockIdx.x * 128;

    // kick W chunks 0 and 1 (8 TMA sub-box loads each: 64k x 32n, SW128)
    if (tid == 0) {
#pragma unroll
        for (int s = 0; s < 2; s++) {
            MBARRIER_EXPECT_TX(sb + SM_FULL + 8 * s, W_CHUNK_BYTES);
#pragma unroll
            for (int kb = 0; kb < 8; kb++)
                TMA_LOAD_2D(sb + SM_W + s * W_CHUNK_BYTES + kb * 4096, &tma_w,
                            kb * 64, s * N_CHUNK, sb + SM_FULL + 8 * s);
        }
    }

    // load + convert A tile: x[m0:m0+128, 0:512] fp32 -> bf16 SW128 smem
    {
        const float4* xg = (const float4*)(x + (size_t)m0 * DD);
#pragma unroll 8
        for (int i = 0; i < 64; i++) {
            int idx = tid + i * 256;
            int r = idx >> 7, c4 = idx & 127;
            float4 f = xg[(size_t)r * 128 + c4];
            __nv_bfloat162 lo = __floats2bfloat162_rn(f.x, f.y);
            __nv_bfloat162 hi = __floats2bfloat162_rn(f.z, f.w);
            int k = c4 * 4;
            uint32_t off = (uint32_t)SM_A + (uint32_t)(k >> 6) * 16384u + swz(r, (k & 63) * 2);
            uint2 u;
            u.x = *reinterpret_cast<uint32_t*>(&lo);
            u.y = *reinterpret_cast<uint32_t*>(&hi);
            *reinterpret_cast<uint2*>(smem + off) = u;
        }
    }
    __syncthreads();

    // ---- pull this warp's A fragments into registers (whole K=512) ----
    // warp w owns rows m0 + w*16 .. +15.  32 ksteps x 4 regs = 128 regs.
    uint32_t areg[8][4][4];
    {
        uint32_t row  = (uint32_t)wid * 16 + (lane & 15);
        uint32_t abase = sb + SM_A + row * 128u;
        uint32_t axor  = ((row & 7u) << 4) ^ ((uint32_t)(lane >> 4) << 4);
#pragma unroll
        for (int kb = 0; kb < 8; kb++)
#pragma unroll
            for (int kq = 0; kq < 4; kq++)
                ldsm_x4(areg[kb][kq], abase + (uint32_t)kb * 16384u + (((uint32_t)kq * 32u) ^ axor));
    }

    // B ldmatrix address pieces (x4 covers 16 n-rows x k16)
    // lanes 0-7: n 0-7 @k, 8-15: n 0-7 @k+8, 16-23: n 8-15 @k, 24-31: n 8-15 @k+8
    uint32_t nrow_lo = (lane & 7u) + (((uint32_t)lane >> 4) << 3);
    uint32_t brow = nrow_lo * 128u;
    uint32_t bxor = ((((uint32_t)lane >> 3) & 1u) << 4) ^ ((nrow_lo & 7u) << 4);

    float score0 = 0.f, score1 = 0.f;

    for (int chunk = 0; chunk < N_CHUNKS; chunk++) {
        const int buf = chunk & 1;
        const int ph  = (chunk >> 1) & 1;
        const uint32_t wb = sb + SM_W + buf * W_CHUNK_BYTES;

        MBARRIER_WAIT_PARITY(sb + SM_FULL + 8 * buf, ph);

        float acc[4][4];
#pragma unroll
        for (int i = 0; i < 4; i++)
#pragma unroll
            for (int j = 0; j < 4; j++) acc[i][j] = 0.f;

        // K loop: 8 sub-boxes x 4 k16-steps; B-only smem traffic
#pragma unroll
        for (int kb = 0; kb < 8; kb++) {
            const uint32_t wkb = wb + (uint32_t)kb * 4096u + brow;
#pragma unroll
            for (int kq = 0; kq < 4; kq++) {
                const uint32_t kc = (uint32_t)kq * 32u;
                uint32_t b0[4], b1[4];
                ldsm_x4(b0, wkb + (kc ^ bxor));          // n 0-15 of chunk
                ldsm_x4(b1, wkb + 2048u + (kc ^ bxor));  // n 16-31 of chunk
                mma_bf16(acc[0], areg[kb][kq], b0);
                mma_bf16(acc[1], areg[kb][kq], b0 + 2);
                mma_bf16(acc[2], areg[kb][kq], b1);
                mma_bf16(acc[3], areg[kb][kq], b1 + 2);
            }
        }

        // epilogue: tanh + dot with v
        {
            const int jb = chunk * N_CHUNK + (lane & 3) * 2;
#pragma unroll
            for (int g = 0; g < 4; g++) {
                float v0 = vsh[jb + g * 8];
                float v1 = vsh[jb + g * 8 + 1];
                score0 += tanh_approx(acc[g][0]) * v0 + tanh_approx(acc[g][1]) * v1;
                score1 += tanh_approx(acc[g][2]) * v0 + tanh_approx(acc[g][3]) * v1;
            }
        }

        __syncthreads();  // all warps done reading this W buffer
        if (chunk + 2 < N_CHUNKS && tid == 0) {
            MBARRIER_EXPECT_TX(sb + SM_FULL + 8 * buf, W_CHUNK_BYTES);
#pragma unroll
            for (int kb = 0; kb < 8; kb++)
                TMA_LOAD_2D(wb + kb * 4096, &tma_w,
                            kb * 64, (chunk + 2) * N_CHUNK, sb + SM_FULL + 8 * buf);
        }
    }

    // reduce over n: lanes sharing a row differ only in (lane&3)
    score0 += __shfl_xor_sync(0xFFFFFFFF, score0, 1);
    score0 += __shfl_xor_sync(0xFFFFFFFF, score0, 2);
    score1 += __shfl_xor_sync(0xFFFFFFFF, score1, 1);
    score1 += __shfl_xor_sync(0xFFFFFFFF, score1, 2);
    if ((lane & 3) == 0) {
        int r = m0 + wid * 16 + (lane >> 2);
        g_scores[r]     = score0;
        g_scores[r + 8] = score1;
    }
}

// ---------------- kernel 2: per-batch softmax stats (max, 1/sumexp) ----------
__global__ void k2_stats() {
    int b = blockIdx.x;
    __shared__ float red[256];
    float m = -1e30f;
    for (int t = threadIdx.x; t < TT; t += 256) m = fmaxf(m, g_scores[b * TT + t]);
    red[threadIdx.x] = m; __syncthreads();
    for (int s = 128; s > 0; s >>= 1) {
        if (threadIdx.x < s) red[threadIdx.x] = fmaxf(red[threadIdx.x], red[threadIdx.x + s]);
        __syncthreads();
    }
    float mx = red[0]; __syncthreads();
    float sum = 0.0f;
    for (int t = threadIdx.x; t < TT; t += 256) sum += __expf(g_scores[b * TT + t] - mx);
    red[threadIdx.x] = sum; __syncthreads();
    for (int s = 128; s > 0; s >>= 1) {
        if (threadIdx.x < s) red[threadIdx.x] += red[threadIdx.x + s];
        __syncthreads();
    }
    if (threadIdx.x == 0) { g_stats[2 * b] = mx; g_stats[2 * b + 1] = 1.0f / red[0]; }
}

// ---------------- kernel 3: weighted-sum pooling (fp32, vectorized) ----------
// grid (64 t-chunks of 64, 16 batches), 128 threads; thread owns one float4 col.
__global__ void __launch_bounds__(128) k3_pool(const float* __restrict__ x,
                                               float* __restrict__ out) {
    int b = blockIdx.y;
    int t0 = blockIdx.x * 64;
    __shared__ float w_s[64];
    float mx = g_stats[2 * b], inv = g_stats[2 * b + 1];
    if (threadIdx.x < 64)
        w_s[threadIdx.x] = __expf(g_scores[b * TT + t0 + threadIdx.x] - mx) * inv;
    __syncthreads();
    const float4* xp = (const float4*)(x + ((size_t)b * TT + t0) * DD) + threadIdx.x;
    float ax = 0.f, ay = 0.f, az = 0.f, aw = 0.f;
    float bx_ = 0.f, by = 0.f, bz = 0.f, bw = 0.f;
#pragma unroll 16
    for (int i = 0; i < 64; i += 2) {
        float4 f0 = xp[(size_t)i * 128];
        float4 f1 = xp[(size_t)(i + 1) * 128];
        float w0 = w_s[i], w1 = w_s[i + 1];
        ax = fmaf(w0, f0.x, ax); ay = fmaf(w0, f0.y, ay);
        az = fmaf(w0, f0.z, az); aw = fmaf(w0, f0.w, aw);
        bx_ = fmaf(w1, f1.x, bx_); by = fmaf(w1, f1.y, by);
        bz = fmaf(w1, f1.z, bz); bw = fmaf(w1, f1.w, bw);
    }
    float* o = out + b * DD + threadIdx.x * 4;
    atomicAdd(o + 0, ax + bx_); atomicAdd(o + 1, ay + by);
    atomicAdd(o + 2, az + bz); atomicAdd(o + 3, aw + bw);
}

// ---------------- host ----------------
typedef CUresult (*EncodeTiledFn)(
    CUtensorMap*, CUtensorMapDataType, cuuint32_t, void*,
    const cuuint64_t*, const cuuint64_t*, const cuuint32_t*, const cuuint32_t*,
    CUtensorMapInterleave, CUtensorMapSwizzle, CUtensorMapL2promotion, CUtensorMapFloatOOBfill);

extern "C" void kernel_launch(void* const* d_in, const int* in_sizes, int n_in,
                              void* d_out, int out_size) {
    const float* x = (const float*)d_in[0];
    const float* W = (const float*)d_in[1];
    const float* v = (const float*)d_in[2];
    float* out = (float*)d_out;

    // driver TMA-encode entry point through the runtime (no -lcuda link needed)
    EncodeTiledFn encode = nullptr;
    cudaDriverEntryPointQueryResult qres;
    cudaGetDriverEntryPointByVersion("cuTensorMapEncodeTiled", (void**)&encode,
                                     12000, cudaEnableDefault, &qres);

    void* wbf_ptr = nullptr;
    cudaGetSymbolAddress(&wbf_ptr, g_Wbf);

    // transpose+convert W -> g_Wbf[e][d] bf16
    k0_transpose<<<dim3(16, 16), 256>>>(W);

    // TMA map for W: dims (k=512, n=512) bf16, box (64, 32), SW128
    CUtensorMap tma_w{};
    if (encode) {
        cuuint64_t dims[2]    = { (cuuint64_t)DD, (cuuint64_t)EE };
        cuuint64_t strides[1] = { (cuuint64_t)DD * sizeof(__nv_bfloat16) };
        cuuint32_t box[2]     = { 64, N_CHUNK };
        cuuint32_t es[2]      = { 1, 1 };
        encode(&tma_w, CU_TENSOR_MAP_DATA_TYPE_BFLOAT16, 2, wbf_ptr,
               dims, strides, box, es,
               CU_TENSOR_MAP_INTERLEAVE_NONE, CU_TENSOR_MAP_SWIZZLE_128B,
               CU_TENSOR_MAP_L2_PROMOTION_L2_128B, CU_TENSOR_MAP_FLOAT_OOB_FILL_NONE);
    }

    cudaFuncSetAttribute(k1_gemm_scores, cudaFuncAttributeMaxDynamicSharedMemorySize, SM_TOTAL1);
    k1_gemm_scores<<<MTOT / 128, 256, SM_TOTAL1>>>(tma_w, x, v);

    k2_stats<<<BB, 256>>>();

    cudaMemsetAsync(d_out, 0, (size_t)out_size * sizeof(float));
    k3_pool<<<dim3(TT / 64, BB), 128>>>(x, out);
}